// round 17
// baseline (speedup 1.0000x reference)
#include <cuda_runtime.h>
#include <math_constants.h>

// RMAC: x [64,512,32,32] fp32 -> out [64,512,1,1]
// Row/col ranges (H=W=32, L=3): R0=[0,32) R1=[0,21) R2=[11,32) R3=[0,16) R4=[8,24) R5=[16,32)
// 14 regions: (R0,R0) w=2 (global + l=1), 2x2 over {R1,R2}, 3x3 over {R3,R4,R5}.
// out[b,c] = sum_r w_r * M[b,r,c] / (sqrt(SS[b,r]) + 1e-6)
//
// Stage1: 4096 blocks x 256 threads (8 warps, warp-per-map) — halves per-block
// fixed cost + RED count vs 8192x128. PDL trigger at block start (R16 win).
// Stage2: PDL secondary, hoisted g_M loads, warp-local s_inv (no smem bar).

#define NREG 14

__device__ float g_M[64 * NREG * 512];   // [b][r][ch]
__device__ float g_SS[64 * NREG];        // region sums of squares (RED atomics);
                                         // zero at load, re-zeroed by stage2.

struct __align__(16) SmemT {
    float s2[8][6][36];    // [warp][range][col] (pad 36)
    float ssq[8][16];      // per-warp region squares
};

__device__ __forceinline__ float4 f4max(float4 a, float4 b) {
    return make_float4(fmaxf(a.x, b.x), fmaxf(a.y, b.y), fmaxf(a.z, b.z), fmaxf(a.w, b.w));
}
__device__ __forceinline__ float4 shflx4(float4 v, int m) {
    float4 r;
    r.x = __shfl_xor_sync(0xffffffffu, v.x, m);
    r.y = __shfl_xor_sync(0xffffffffu, v.y, m);
    r.z = __shfl_xor_sync(0xffffffffu, v.z, m);
    r.w = __shfl_xor_sync(0xffffffffu, v.w, m);
    return r;
}

// Warp per (b,c) map. Lane l: q = l>>3 (row phase), c0 = l&7 (4-col group).
// float4 k covers row 4k+q, cols 4c0..4c0+3. 8x LDG.128 fully coalesced.
__global__ __launch_bounds__(256, 4) void rmac_stage1(const float* __restrict__ x) {
    __shared__ SmemT sm;
    const int tid  = threadIdx.x;
    const int w    = tid >> 5;
    const int lane = tid & 31;
    const int wid  = blockIdx.x * 8 + w;      // (b,c) map index
    const int q    = lane >> 3;
    const int c0   = lane & 7;

    // PDL trigger at block start: dependent grid launches when the last wave
    // STARTS (R16: measured win vs trigger-at-end).
    asm volatile("griddepcontrol.launch_dependents;");

    const float4* __restrict__ p = (const float4*)x + (size_t)wid * 256 + lane;

    float4 v0 = __ldcs(p +   0), v1 = __ldcs(p +  32);
    float4 v2 = __ldcs(p +  64), v3 = __ldcs(p +  96);
    float4 v4 = __ldcs(p + 128), v5 = __ldcs(p + 160);
    float4 v6 = __ldcs(p + 192), v7 = __ldcs(p + 224);

    float4 pc = f4max(v2, v3);                 // rows [8,16)
    float4 pd = f4max(v4, v5);                 // rows [16,24)
    float4 g3 = f4max(f4max(v0, v1), pc);      // rows [0,16)
    float4 g5 = f4max(pd, f4max(v6, v7));      // rows [16,32)
    float4 pb = (q == 3) ? pc : v3;            // rows [11,16): row 11 = k2,q3
    float4 pa = (q == 0) ? pd : v4;            // rows [16,21): row 20 = k5,q0

    float4 m0 = f4max(g3, g5);   // [0,32)
    float4 m1 = f4max(g3, pa);   // [0,21)
    float4 m2 = f4max(pb, g5);   // [11,32)
    float4 m3 = g3;              // [0,16)
    float4 m4 = f4max(pc, pd);   // [8,24)
    float4 m5 = g5;              // [16,32)

    // Butterfly over row-phase q (lane bits 3,4): full column maxes in all lanes.
    m0 = f4max(m0, shflx4(m0, 8)); m0 = f4max(m0, shflx4(m0, 16));
    m1 = f4max(m1, shflx4(m1, 8)); m1 = f4max(m1, shflx4(m1, 16));
    m2 = f4max(m2, shflx4(m2, 8)); m2 = f4max(m2, shflx4(m2, 16));
    m3 = f4max(m3, shflx4(m3, 8)); m3 = f4max(m3, shflx4(m3, 16));
    m4 = f4max(m4, shflx4(m4, 8)); m4 = f4max(m4, shflx4(m4, 16));
    m5 = f4max(m5, shflx4(m5, 8)); m5 = f4max(m5, shflx4(m5, 16));

    if (q == 0) {   // lanes 0..7 publish col maxes (c0 == lane)
        *(float4*)&sm.s2[w][0][c0 << 2] = m0;
        *(float4*)&sm.s2[w][1][c0 << 2] = m1;
        *(float4*)&sm.s2[w][2][c0 << 2] = m2;
        *(float4*)&sm.s2[w][3][c0 << 2] = m3;
        *(float4*)&sm.s2[w][4][c0 << 2] = m4;
        *(float4*)&sm.s2[w][5][c0 << 2] = m5;
    }
    __syncwarp();

    if (lane < NREG) {
        int R, Cc;
        if (lane == 0)     { R = 0; Cc = 0; }
        else if (lane < 5) { R = 1 + ((lane - 1) >> 1); Cc = 1 + ((lane - 1) & 1); }
        else               { int t = lane - 5; R = 3 + t / 3; Cc = 3 + t % 3; }
        const int cs = (Cc == 2) ? 11 : (Cc == 4) ? 8 : (Cc == 5) ? 16 : 0;
        const int ce = (Cc == 1) ? 21 : (Cc == 3) ? 16 : (Cc == 4) ? 24 : 32;
        float mm = -CUDART_INF_F;
        for (int j = cs; j < ce; ++j)
            mm = fmaxf(mm, sm.s2[w][R][j]);
        const int b = wid >> 9, ch = wid & 511;
        g_M[(b * NREG + lane) * 512 + ch] = mm;
        sm.ssq[w][lane] = mm * mm;
    }
    __syncthreads();

    if (tid < NREG) {   // one RED per (block, region); 64 blocks per batch
        const int b = blockIdx.x >> 6;
        float t = 0.0f;
#pragma unroll
        for (int ww = 0; ww < 8; ++ww) t += sm.ssq[ww][tid];
        atomicAdd(&g_SS[b * NREG + tid], t);
    }
}

// PDL secondary: scheduled during stage1's last wave; HW-waits for completion.
// s_inv computed warp-locally (lane<14 loads+rsqrt, then shuffles distribute) —
// no smem round-trip / block barrier on the post-wait critical path.
__global__ __launch_bounds__(256) void rmac_stage2(float* __restrict__ out) {
    const int b    = blockIdx.x >> 1;
    const int ch   = ((blockIdx.x & 1) << 8) + threadIdx.x;
    const int lane = threadIdx.x & 31;

    const float* __restrict__ base = g_M + b * NREG * 512 + ch;   // prelude

    asm volatile("griddepcontrol.wait;" ::: "memory");

    // 14 independent g_M loads issued first
    float v[NREG];
#pragma unroll
    for (int r = 0; r < NREG; ++r)
        v[r] = base[r * 512];

    // each warp computes s_inv redundantly: lane r<14 owns region r
    float my_inv = 0.0f;
    if (lane < NREG)
        my_inv = 1.0f / (sqrtf(g_SS[b * NREG + lane]) + 1e-6f);

    float acc = 0.0f;
#pragma unroll
    for (int r = 0; r < NREG; ++r) {
        float si = __shfl_sync(0xffffffffu, my_inv, r);
        acc += ((r == 0) ? 2.0f : 1.0f) * v[r] * si;
    }
    out[b * 512 + ch] = acc;

    // re-zero g_SS for next graph replay (off critical path; one warp per block
    // suffices — values already consumed by every warp's own loads above).
    if (threadIdx.x < NREG)
        g_SS[b * NREG + threadIdx.x] = 0.0f;
}

extern "C" void kernel_launch(void* const* d_in, const int* in_sizes, int n_in,
                              void* d_out, int out_size) {
    const float* x = (const float*)d_in[0];
    float* out = (float*)d_out;

    rmac_stage1<<<4096, 256>>>(x);

    cudaLaunchConfig_t cfg = {};
    cfg.gridDim  = dim3(128, 1, 1);
    cfg.blockDim = dim3(256, 1, 1);
    cfg.dynamicSmemBytes = 0;
    cfg.stream = 0;
    cudaLaunchAttribute attr[1];
    attr[0].id = cudaLaunchAttributeProgrammaticStreamSerialization;
    attr[0].val.programmaticStreamSerializationAllowed = 1;
    cfg.attrs = attr;
    cfg.numAttrs = 1;
    cudaLaunchKernelEx(&cfg, rmac_stage2, out);
}